// round 14
// baseline (speedup 1.0000x reference)
#include <cuda_runtime.h>
#include <cuda_fp16.h>
#include <cstdint>

#define BB 64
#define EE 1024
#define NN_ 512
#define DD 64
#define HH 128
#define TT 5

// fp16-packed scratch (word = half2): edge_feature
__device__ uint32_t g_efh[BB * EE * (DD / 2)];   // 8 MB

// ---------------------------------------------------------------------------
// helpers
// ---------------------------------------------------------------------------
__device__ __forceinline__ uint32_t h2(float lo, float hi) {
    __half2 h = __floats2half2_rn(lo, hi);
    return *reinterpret_cast<uint32_t*>(&h);
}
__device__ __forceinline__ uint32_t sm_u32(const void* p) {
    return (uint32_t)__cvta_generic_to_shared(p);
}
__device__ __forceinline__ void ldsm4(uint32_t& r0, uint32_t& r1, uint32_t& r2,
                                      uint32_t& r3, uint32_t addr) {
    asm volatile("ldmatrix.sync.aligned.m8n8.x4.shared.b16 {%0,%1,%2,%3}, [%4];"
                 : "=r"(r0), "=r"(r1), "=r"(r2), "=r"(r3) : "r"(addr));
}
__device__ __forceinline__ void mma16(float* c, uint32_t a0, uint32_t a1,
                                      uint32_t a2, uint32_t a3,
                                      uint32_t b0, uint32_t b1) {
    asm volatile(
        "mma.sync.aligned.m16n8k16.row.col.f32.f16.f16.f32 "
        "{%0,%1,%2,%3}, {%4,%5,%6,%7}, {%8,%9}, {%0,%1,%2,%3};"
        : "+f"(c[0]), "+f"(c[1]), "+f"(c[2]), "+f"(c[3])
        : "r"(a0), "r"(a1), "r"(a2), "r"(a3), "r"(b0), "r"(b1));
}

// ---------------------------------------------------------------------------
// KF: fused (edges = H @ ori) + per-type MLP mixture. (round-10 winner, as-is)
// ---------------------------------------------------------------------------
#define XS_W    (128 * 36)
#define K1_AW   36
#define K1_BW   72
#define K1_ASZ  (128 * K1_AW)    // 4608 w
#define K1_BSZ  (32 * K1_BW)     // 2304 w
#define K1_BUF  (K1_ASZ + K1_BSZ)
#define W1_PW   (32 * 136)       // one parity: [32 kp(d)][136w n(h)]
#define W2_PW   (64 * 72)        // one parity: [64 kp(h)][72w n(d)]
#define K2_REGION_W (2 * W1_PW + 2 * W2_PW + 640 + 256 + 128)
#define KF_REGION_W (K2_REGION_W > 2 * K1_BUF ? K2_REGION_W : 2 * K1_BUF)
#define KF_SMEM_BYTES ((XS_W + KF_REGION_W) * 4)

__device__ __forceinline__ void stage_w(
    const float* __restrict__ W1, const float* __restrict__ W2,
    const float* __restrict__ b1, const float* __restrict__ b2,
    int tt, int par, uint32_t* W1s, uint32_t* W2s,
    float* b1s, float* b2s, int tid) {
    const float* w1 = W1 + (size_t)tt * DD * HH;
    const float* w2 = W2 + (size_t)tt * HH * DD;
#pragma unroll
    for (int p = 0; p < 4; p++) {
        int s = tid + p * 256;
        {   // W1 [64][128] -> kpair-packed [32][136w]
            int r = s >> 5, cq = s & 31;
            float4 f0 = *(const float4*)(w1 + (size_t)(2 * r) * HH + cq * 4);
            float4 f1 = *(const float4*)(w1 + (size_t)(2 * r + 1) * HH + cq * 4);
            uint4 w;
            w.x = h2(f0.x, f1.x); w.y = h2(f0.y, f1.y);
            w.z = h2(f0.z, f1.z); w.w = h2(f0.w, f1.w);
            *(uint4*)&W1s[par * W1_PW + r * 136 + cq * 4] = w;
        }
        {   // W2 [128][64] -> kpair-packed [64][72w]
            int r = s >> 4, cq = s & 15;
            float4 f0 = *(const float4*)(w2 + (size_t)(2 * r) * DD + cq * 4);
            float4 f1 = *(const float4*)(w2 + (size_t)(2 * r + 1) * DD + cq * 4);
            uint4 w;
            w.x = h2(f0.x, f1.x); w.y = h2(f0.y, f1.y);
            w.z = h2(f0.z, f1.z); w.w = h2(f0.w, f1.w);
            *(uint4*)&W2s[par * W2_PW + r * 72 + cq * 4] = w;
        }
    }
    if (tid < 128)      b1s[par * 128 + tid]        = b1[tt * HH + tid];
    else if (tid < 192) b2s[par * 64 + (tid - 128)] = b2[tt * DD + (tid - 128)];
}

__global__ __launch_bounds__(256, 2) void kf_fused(
    const float* __restrict__ H,  const float* __restrict__ ori,
    const float* __restrict__ ed, const float* __restrict__ W1,
    const float* __restrict__ b1, const float* __restrict__ W2,
    const float* __restrict__ b2) {
    extern __shared__ uint32_t smw[];
    uint32_t* Xs     = smw;          // [128][36w] persistent
    uint32_t* region = smw + XS_W;

    const int b    = blockIdx.x >> 3;
    const int m0   = (blockIdx.x & 7) * 128;
    const size_t row0 = (size_t)blockIdx.x * 128;
    const int tid  = threadIdx.x;
    const int wid  = tid >> 5, lane = tid & 31;
    const int g = lane >> 2, t = lane & 3;
    const int l15 = lane & 15, lq = lane >> 4;
    const int wm1 = (wid >> 1) * 32, wn1 = (wid & 1) * 32;

    // ================= phase 1: edges tile = H[b] tile @ ori[b], kc=64 ======
    {
        const float* Hb   = H   + (size_t)b * EE * NN_;
        const float* orib = ori + (size_t)b * NN_ * DD;

        float acc[2][4][4];
#pragma unroll
        for (int mi = 0; mi < 2; mi++)
#pragma unroll
            for (int ni = 0; ni < 4; ni++)
#pragma unroll
                for (int jj = 0; jj < 4; jj++) acc[mi][ni][jj] = 0.f;

        const int br = tid >> 4, bcq = tid & 15;

        const uint32_t smP1 = sm_u32(region);
        const uint32_t offA = ((wm1 + l15) * K1_AW + 4 * lq) * 4;

        float4 ra[8], rb[4];
#pragma unroll
        for (int p = 0; p < 8; p++) {
            int f = tid + p * 256;
            ra[p] = *(const float4*)(Hb + (size_t)(m0 + (f >> 4)) * NN_ + (f & 15) * 4);
        }
#pragma unroll
        for (int q = 0; q < 2; q++) {
            int r = br + 16 * q;
            rb[2 * q]     = *(const float4*)(orib + (size_t)(2 * r) * DD + bcq * 4);
            rb[2 * q + 1] = *(const float4*)(orib + (size_t)(2 * r + 1) * DD + bcq * 4);
        }
        {
            uint32_t* A0 = region; uint32_t* B0 = region + K1_ASZ;
#pragma unroll
            for (int p = 0; p < 8; p++) {
                int f = tid + p * 256;
                uint2 w; w.x = h2(ra[p].x, ra[p].y); w.y = h2(ra[p].z, ra[p].w);
                *(uint2*)&A0[(f >> 4) * K1_AW + (f & 15) * 2] = w;
            }
#pragma unroll
            for (int q = 0; q < 2; q++) {
                int r = br + 16 * q;
                uint4 w;
                w.x = h2(rb[2 * q].x, rb[2 * q + 1].x);
                w.y = h2(rb[2 * q].y, rb[2 * q + 1].y);
                w.z = h2(rb[2 * q].z, rb[2 * q + 1].z);
                w.w = h2(rb[2 * q].w, rb[2 * q + 1].w);
                *(uint4*)&B0[r * K1_BW + bcq * 4] = w;
            }
        }
        __syncthreads();

        int buf = 0;
        for (int k0 = 0; k0 < NN_; k0 += 64) {
            const int kn = k0 + 64;
            if (kn < NN_) {
#pragma unroll
                for (int p = 0; p < 8; p++) {
                    int f = tid + p * 256;
                    ra[p] = *(const float4*)(Hb + (size_t)(m0 + (f >> 4)) * NN_ + kn + (f & 15) * 4);
                }
#pragma unroll
                for (int q = 0; q < 2; q++) {
                    int r = br + 16 * q;
                    rb[2 * q]     = *(const float4*)(orib + (size_t)(kn + 2 * r) * DD + bcq * 4);
                    rb[2 * q + 1] = *(const float4*)(orib + (size_t)(kn + 2 * r + 1) * DD + bcq * 4);
                }
            }
            const uint32_t abase = smP1 + (uint32_t)(buf * (K1_BUF * 4));
            const uint32_t* B_ = region + buf * K1_BUF + K1_ASZ;
#pragma unroll
            for (int kk = 0; kk < 4; kk++) {
                uint32_t a0[4], a1[4], bf[4][2];
                ldsm4(a0[0], a0[1], a0[2], a0[3], abase + offA + kk * 32);
                ldsm4(a1[0], a1[1], a1[2], a1[3], abase + offA + 2304 + kk * 32);
#pragma unroll
                for (int ni = 0; ni < 4; ni++) {
                    bf[ni][0] = B_[(8 * kk + t) * K1_BW + wn1 + 8 * ni + g];
                    bf[ni][1] = B_[(8 * kk + t + 4) * K1_BW + wn1 + 8 * ni + g];
                }
#pragma unroll
                for (int ni = 0; ni < 4; ni++) {
                    mma16(acc[0][ni], a0[0], a0[1], a0[2], a0[3], bf[ni][0], bf[ni][1]);
                    mma16(acc[1][ni], a1[0], a1[1], a1[2], a1[3], bf[ni][0], bf[ni][1]);
                }
            }
            if (kn < NN_) {
                uint32_t* An = region + (buf ^ 1) * K1_BUF;
                uint32_t* Bn = An + K1_ASZ;
#pragma unroll
                for (int p = 0; p < 8; p++) {
                    int f = tid + p * 256;
                    uint2 w; w.x = h2(ra[p].x, ra[p].y); w.y = h2(ra[p].z, ra[p].w);
                    *(uint2*)&An[(f >> 4) * K1_AW + (f & 15) * 2] = w;
                }
#pragma unroll
                for (int q = 0; q < 2; q++) {
                    int r = br + 16 * q;
                    uint4 w;
                    w.x = h2(rb[2 * q].x, rb[2 * q + 1].x);
                    w.y = h2(rb[2 * q].y, rb[2 * q + 1].y);
                    w.z = h2(rb[2 * q].z, rb[2 * q + 1].z);
                    w.w = h2(rb[2 * q].w, rb[2 * q + 1].w);
                    *(uint4*)&Bn[r * K1_BW + bcq * 4] = w;
                }
            }
            __syncthreads();
            buf ^= 1;
        }

        // epilogue: pack acc -> Xs
#pragma unroll
        for (int mi = 0; mi < 2; mi++)
#pragma unroll
            for (int ni = 0; ni < 4; ni++) {
                int r1 = wm1 + 16 * mi + g, r2 = r1 + 8;
                int cw = (wn1 >> 1) + 4 * ni + t;
                Xs[r1 * 36 + cw] = h2(acc[mi][ni][0], acc[mi][ni][1]);
                Xs[r2 * 36 + cw] = h2(acc[mi][ni][2], acc[mi][ni][3]);
            }
    }
    // ================= phase 2 setup ========================================
    uint32_t* W1s = region;
    uint32_t* W2s = region + 2 * W1_PW;
    float* wds = (float*)(W2s + 2 * W2_PW);
    float* b1s = wds + 640;
    float* b2s = b1s + 256;

    const int wm2 = wid * 16;

    for (int f = tid; f < 640; f += 256) wds[f] = ed[row0 * TT + f];
    stage_w(W1, W2, b1, b2, 0, 0, W1s, W2s, b1s, b2s, tid);
    __syncthreads();

    const uint32_t smX = sm_u32(Xs);
    const uint32_t offXA = ((wm2 + l15) * 36 + 4 * lq) * 4;
    uint32_t xa[4][4];
#pragma unroll
    for (int kc = 0; kc < 4; kc++)
        ldsm4(xa[kc][0], xa[kc][1], xa[kc][2], xa[kc][3], smX + offXA + kc * 32);

    float Y[8][4];
#pragma unroll
    for (int ni = 0; ni < 8; ni++)
#pragma unroll
        for (int jj = 0; jj < 4; jj++) Y[ni][jj] = 0.f;

    for (int et = 0; et < TT; et++) {
        const int pb = et & 1;
        if (et + 1 < TT)
            stage_w(W1, W2, b1, b2, et + 1, pb ^ 1, W1s, W2s, b1s, b2s, tid);

        const uint32_t* W1c = W1s + pb * W1_PW;
        const uint32_t* W2c = W2s + pb * W2_PW;

        float acc2[8][4];
#pragma unroll
        for (int ni = 0; ni < 8; ni++)
#pragma unroll
            for (int jj = 0; jj < 4; jj++) acc2[ni][jj] = 0.f;

#pragma unroll
        for (int s = 0; s < 8; s++) {
            float h0a[4] = {0.f, 0.f, 0.f, 0.f};
            float h1a[4] = {0.f, 0.f, 0.f, 0.f};
#pragma unroll
            for (int kc = 0; kc < 4; kc++) {
                uint32_t b00 = W1c[(8 * kc + t) * 136 + 16 * s + g];
                uint32_t b01 = W1c[(8 * kc + t + 4) * 136 + 16 * s + g];
                uint32_t b10 = W1c[(8 * kc + t) * 136 + 16 * s + 8 + g];
                uint32_t b11 = W1c[(8 * kc + t + 4) * 136 + 16 * s + 8 + g];
                mma16(h0a, xa[kc][0], xa[kc][1], xa[kc][2], xa[kc][3], b00, b01);
                mma16(h1a, xa[kc][0], xa[kc][1], xa[kc][2], xa[kc][3], b10, b11);
            }
            float bx0 = b1s[pb * 128 + 16 * s + 2 * t];
            float by0 = b1s[pb * 128 + 16 * s + 2 * t + 1];
            float bx1 = b1s[pb * 128 + 16 * s + 8 + 2 * t];
            float by1 = b1s[pb * 128 + 16 * s + 8 + 2 * t + 1];
            uint32_t af0 = h2(fmaxf(h0a[0] + bx0, 0.f), fmaxf(h0a[1] + by0, 0.f));
            uint32_t af1 = h2(fmaxf(h0a[2] + bx0, 0.f), fmaxf(h0a[3] + by0, 0.f));
            uint32_t af2 = h2(fmaxf(h1a[0] + bx1, 0.f), fmaxf(h1a[1] + by1, 0.f));
            uint32_t af3 = h2(fmaxf(h1a[2] + bx1, 0.f), fmaxf(h1a[3] + by1, 0.f));
#pragma unroll
            for (int ni = 0; ni < 8; ni++) {
                uint32_t b0 = W2c[(8 * s + t) * 72 + 8 * ni + g];
                uint32_t b1v = W2c[(8 * s + t + 4) * 72 + 8 * ni + g];
                mma16(acc2[ni], af0, af1, af2, af3, b0, b1v);
            }
        }
        float wA = wds[(wm2 + g) * TT + et];
        float wB = wds[(wm2 + 8 + g) * TT + et];
#pragma unroll
        for (int ni = 0; ni < 8; ni++) {
            int c = 8 * ni + 2 * t;
            float bx = b2s[pb * 64 + c], by = b2s[pb * 64 + c + 1];
            Y[ni][0] += wA * (acc2[ni][0] + bx);
            Y[ni][1] += wA * (acc2[ni][1] + by);
            Y[ni][2] += wB * (acc2[ni][2] + bx);
            Y[ni][3] += wB * (acc2[ni][3] + by);
        }
        __syncthreads();
    }

    {
        int r1 = (int)row0 + wm2 + g, r2 = r1 + 8;
#pragma unroll
        for (int ni = 0; ni < 8; ni++) {
            g_efh[(size_t)r1 * 32 + 4 * ni + t] = h2(Y[ni][0], Y[ni][1]);
            g_efh[(size_t)r2 * 32 + 4 * ni + t] = h2(Y[ni][2], Y[ni][3]);
        }
    }
}

// ---------------------------------------------------------------------------
// K3 v2 (fixed): node_agg = H^T @ ef + concat ori.
// m-tile 32 -> grid (16, 64) = 1024 CTAs for high occupancy.
// 8 warps = 2m x 4n, warp tile 16x16. e-chunk 64, depth-1 double buffer.
// Hp [epair][m=32] stride 40w; Bp [epair][d=64] stride 72w (row=64w + pad).
// ---------------------------------------------------------------------------
#define K3_HW 40
#define K3_BW 72
#define K3_HSZ (32 * K3_HW)     // 1280 w
#define K3_BSZ (32 * K3_BW)     // 2304 w
#define K3_BUF (K3_HSZ + K3_BSZ)
#define K3_SMEM_BYTES (2 * K3_BUF * 4)   // 28672 B

__global__ __launch_bounds__(256, 5) void k3_out(const float* __restrict__ H,
                                                 const float* __restrict__ ori,
                                                 float* __restrict__ out) {
    extern __shared__ uint32_t sw3[];

    const int b   = blockIdx.y;
    const int n0  = blockIdx.x * 32;
    const int tid = threadIdx.x;
    const int wid = tid >> 5, lane = tid & 31;
    const int g = lane >> 2, t = lane & 3;
    const int wm = (wid >> 2) * 16;        // 2 m-groups
    const int wn = (wid & 3) * 16;         // 4 n-groups

    const float* Hb = H + (size_t)b * EE * NN_;
    const uint32_t* efb = g_efh + (size_t)b * EE * 32;

    float acc[2][4];
#pragma unroll
    for (int ni = 0; ni < 2; ni++)
#pragma unroll
        for (int jj = 0; jj < 4; jj++) acc[ni][jj] = 0.f;

    const int hr = tid >> 3, hq = tid & 7;   // pair-row 0..31, quad 0..7

    float4 ha0, ha1;
    uint4  ea, eb2;
    ha0 = *(const float4*)(Hb + (size_t)(2 * hr) * NN_ + n0 + hq * 4);
    ha1 = *(const float4*)(Hb + (size_t)(2 * hr + 1) * NN_ + n0 + hq * 4);
    ea  = *(const uint4*)&efb[(size_t)(2 * hr) * 32 + hq * 4];
    eb2 = *(const uint4*)&efb[(size_t)(2 * hr + 1) * 32 + hq * 4];
    {
        uint32_t* Hp = sw3; uint32_t* Bp = sw3 + K3_HSZ;
        uint4 wh;
        wh.x = h2(ha0.x, ha1.x); wh.y = h2(ha0.y, ha1.y);
        wh.z = h2(ha0.z, ha1.z); wh.w = h2(ha0.w, ha1.w);
        *(uint4*)&Hp[hr * K3_HW + hq * 4] = wh;
        uint4 w1v, w2v;
        w1v.x = __byte_perm(ea.x, eb2.x, 0x5410);
        w1v.y = __byte_perm(ea.x, eb2.x, 0x7632);
        w1v.z = __byte_perm(ea.y, eb2.y, 0x5410);
        w1v.w = __byte_perm(ea.y, eb2.y, 0x7632);
        w2v.x = __byte_perm(ea.z, eb2.z, 0x5410);
        w2v.y = __byte_perm(ea.z, eb2.z, 0x7632);
        w2v.z = __byte_perm(ea.w, eb2.w, 0x5410);
        w2v.w = __byte_perm(ea.w, eb2.w, 0x7632);
        *(uint4*)&Bp[hr * K3_BW + hq * 8]     = w1v;
        *(uint4*)&Bp[hr * K3_BW + hq * 8 + 4] = w2v;
    }
    __syncthreads();

    int buf = 0;
    for (int e0 = 0; e0 < EE; e0 += 64) {
        const int en = e0 + 64;
        if (en < EE) {
            ha0 = *(const float4*)(Hb + (size_t)(en + 2 * hr) * NN_ + n0 + hq * 4);
            ha1 = *(const float4*)(Hb + (size_t)(en + 2 * hr + 1) * NN_ + n0 + hq * 4);
            ea  = *(const uint4*)&efb[(size_t)(en + 2 * hr) * 32 + hq * 4];
            eb2 = *(const uint4*)&efb[(size_t)(en + 2 * hr + 1) * 32 + hq * 4];
        }
        const uint32_t* Hp = sw3 + buf * K3_BUF;
        const uint32_t* Bp = Hp + K3_HSZ;
#pragma unroll
        for (int kk = 0; kk < 4; kk++) {
            uint32_t a[4], bf[2][2];
            a[0] = Hp[(8 * kk + t) * K3_HW + wm + g];
            a[1] = Hp[(8 * kk + t) * K3_HW + wm + 8 + g];
            a[2] = Hp[(8 * kk + t + 4) * K3_HW + wm + g];
            a[3] = Hp[(8 * kk + t + 4) * K3_HW + wm + 8 + g];
#pragma unroll
            for (int ni = 0; ni < 2; ni++) {
                bf[ni][0] = Bp[(8 * kk + t) * K3_BW + wn + 8 * ni + g];
                bf[ni][1] = Bp[(8 * kk + t + 4) * K3_BW + wn + 8 * ni + g];
            }
#pragma unroll
            for (int ni = 0; ni < 2; ni++)
                mma16(acc[ni], a[0], a[1], a[2], a[3], bf[ni][0], bf[ni][1]);
        }
        if (en < EE) {
            uint32_t* Hn = sw3 + (buf ^ 1) * K3_BUF;
            uint32_t* Bn = Hn + K3_HSZ;
            uint4 wh;
            wh.x = h2(ha0.x, ha1.x); wh.y = h2(ha0.y, ha1.y);
            wh.z = h2(ha0.z, ha1.z); wh.w = h2(ha0.w, ha1.w);
            *(uint4*)&Hn[hr * K3_HW + hq * 4] = wh;
            uint4 w1v, w2v;
            w1v.x = __byte_perm(ea.x, eb2.x, 0x5410);
            w1v.y = __byte_perm(ea.x, eb2.x, 0x7632);
            w1v.z = __byte_perm(ea.y, eb2.y, 0x5410);
            w1v.w = __byte_perm(ea.y, eb2.y, 0x7632);
            w2v.x = __byte_perm(ea.z, eb2.z, 0x5410);
            w2v.y = __byte_perm(ea.z, eb2.z, 0x7632);
            w2v.z = __byte_perm(ea.w, eb2.w, 0x5410);
            w2v.w = __byte_perm(ea.w, eb2.w, 0x7632);
            *(uint4*)&Bn[hr * K3_BW + hq * 8]     = w1v;
            *(uint4*)&Bn[hr * K3_BW + hq * 8 + 4] = w2v;
        }
        __syncthreads();
        buf ^= 1;
    }

    float*       outb = out + (size_t)b * NN_ * (2 * DD);
    const float* orib = ori + (size_t)b * NN_ * DD;
#pragma unroll
    for (int ni = 0; ni < 2; ni++) {
        int r1 = n0 + wm + g, r2 = r1 + 8;
        int c  = wn + 8 * ni + 2 * t;
        *(float2*)(outb + (size_t)r1 * (2 * DD) + c) =
            make_float2(acc[ni][0], acc[ni][1]);
        *(float2*)(outb + (size_t)r2 * (2 * DD) + c) =
            make_float2(acc[ni][2], acc[ni][3]);
    }
    // concat half: copy ori rows (32 x 64 = 512 float4, 2/thread)
#pragma unroll
    for (int p = 0; p < 2; p++) {
        int f = tid + p * 256;
        int r = f >> 4, cq = f & 15;
        float4 v = *(const float4*)(orib + (size_t)(n0 + r) * DD + cq * 4);
        *(float4*)(outb + (size_t)(n0 + r) * (2 * DD) + DD + cq * 4) = v;
    }
}

// ---------------------------------------------------------------------------
extern "C" void kernel_launch(void* const* d_in, const int* in_sizes, int n_in,
                              void* d_out, int out_size) {
    const float* ed  = (const float*)d_in[0];
    const float* H   = (const float*)d_in[1];
    const float* ori = (const float*)d_in[2];
    const float* W1  = (const float*)d_in[3];
    const float* b1  = (const float*)d_in[4];
    const float* W2  = (const float*)d_in[5];
    const float* b2  = (const float*)d_in[6];
    float* out = (float*)d_out;

    cudaFuncSetAttribute(kf_fused, cudaFuncAttributeMaxDynamicSharedMemorySize,
                         KF_SMEM_BYTES);

    kf_fused<<<(BB * EE) / 128, 256, KF_SMEM_BYTES>>>(H, ori, ed, W1, b1, W2, b2);

    dim3 g3(NN_ / 32, BB);
    k3_out<<<g3, 256, K3_SMEM_BYTES>>>(H, ori, out);
}

// round 15
// speedup vs baseline: 1.1048x; 1.1048x over previous
#include <cuda_runtime.h>
#include <cuda_fp16.h>
#include <cstdint>

#define BB 64
#define EE 1024
#define NN_ 512
#define DD 64
#define HH 128
#define TT 5

// fp16-packed scratch (word = half2): edge_feature
__device__ uint32_t g_efh[BB * EE * (DD / 2)];   // 8 MB

// ---------------------------------------------------------------------------
// helpers
// ---------------------------------------------------------------------------
__device__ __forceinline__ uint32_t h2(float lo, float hi) {
    __half2 h = __floats2half2_rn(lo, hi);
    return *reinterpret_cast<uint32_t*>(&h);
}
__device__ __forceinline__ uint32_t sm_u32(const void* p) {
    return (uint32_t)__cvta_generic_to_shared(p);
}
__device__ __forceinline__ void ldsm4(uint32_t& r0, uint32_t& r1, uint32_t& r2,
                                      uint32_t& r3, uint32_t addr) {
    asm volatile("ldmatrix.sync.aligned.m8n8.x4.shared.b16 {%0,%1,%2,%3}, [%4];"
                 : "=r"(r0), "=r"(r1), "=r"(r2), "=r"(r3) : "r"(addr));
}
__device__ __forceinline__ void mma16(float* c, uint32_t a0, uint32_t a1,
                                      uint32_t a2, uint32_t a3,
                                      uint32_t b0, uint32_t b1) {
    asm volatile(
        "mma.sync.aligned.m16n8k16.row.col.f32.f16.f16.f32 "
        "{%0,%1,%2,%3}, {%4,%5,%6,%7}, {%8,%9}, {%0,%1,%2,%3};"
        : "+f"(c[0]), "+f"(c[1]), "+f"(c[2]), "+f"(c[3])
        : "r"(a0), "r"(a1), "r"(a2), "r"(a3), "r"(b0), "r"(b1));
}

// ---------------------------------------------------------------------------
// KF: fused (edges = H @ ori) + per-type MLP mixture (round-10 winner)
// + ori concat copy in the epilogue (moved out of K3).
// ---------------------------------------------------------------------------
#define XS_W    (128 * 36)
#define K1_AW   36
#define K1_BW   72
#define K1_ASZ  (128 * K1_AW)    // 4608 w
#define K1_BSZ  (32 * K1_BW)     // 2304 w
#define K1_BUF  (K1_ASZ + K1_BSZ)
#define W1_PW   (32 * 136)       // one parity: [32 kp(d)][136w n(h)]
#define W2_PW   (64 * 72)        // one parity: [64 kp(h)][72w n(d)]
#define K2_REGION_W (2 * W1_PW + 2 * W2_PW + 640 + 256 + 128)
#define KF_REGION_W (K2_REGION_W > 2 * K1_BUF ? K2_REGION_W : 2 * K1_BUF)
#define KF_SMEM_BYTES ((XS_W + KF_REGION_W) * 4)

__device__ __forceinline__ void stage_w(
    const float* __restrict__ W1, const float* __restrict__ W2,
    const float* __restrict__ b1, const float* __restrict__ b2,
    int tt, int par, uint32_t* W1s, uint32_t* W2s,
    float* b1s, float* b2s, int tid) {
    const float* w1 = W1 + (size_t)tt * DD * HH;
    const float* w2 = W2 + (size_t)tt * HH * DD;
#pragma unroll
    for (int p = 0; p < 4; p++) {
        int s = tid + p * 256;
        {   // W1 [64][128] -> kpair-packed [32][136w]
            int r = s >> 5, cq = s & 31;
            float4 f0 = *(const float4*)(w1 + (size_t)(2 * r) * HH + cq * 4);
            float4 f1 = *(const float4*)(w1 + (size_t)(2 * r + 1) * HH + cq * 4);
            uint4 w;
            w.x = h2(f0.x, f1.x); w.y = h2(f0.y, f1.y);
            w.z = h2(f0.z, f1.z); w.w = h2(f0.w, f1.w);
            *(uint4*)&W1s[par * W1_PW + r * 136 + cq * 4] = w;
        }
        {   // W2 [128][64] -> kpair-packed [64][72w]
            int r = s >> 4, cq = s & 15;
            float4 f0 = *(const float4*)(w2 + (size_t)(2 * r) * DD + cq * 4);
            float4 f1 = *(const float4*)(w2 + (size_t)(2 * r + 1) * DD + cq * 4);
            uint4 w;
            w.x = h2(f0.x, f1.x); w.y = h2(f0.y, f1.y);
            w.z = h2(f0.z, f1.z); w.w = h2(f0.w, f1.w);
            *(uint4*)&W2s[par * W2_PW + r * 72 + cq * 4] = w;
        }
    }
    if (tid < 128)      b1s[par * 128 + tid]        = b1[tt * HH + tid];
    else if (tid < 192) b2s[par * 64 + (tid - 128)] = b2[tt * DD + (tid - 128)];
}

__global__ __launch_bounds__(256, 2) void kf_fused(
    const float* __restrict__ H,  const float* __restrict__ ori,
    const float* __restrict__ ed, const float* __restrict__ W1,
    const float* __restrict__ b1, const float* __restrict__ W2,
    const float* __restrict__ b2, float* __restrict__ out) {
    extern __shared__ uint32_t smw[];
    uint32_t* Xs     = smw;          // [128][36w] persistent
    uint32_t* region = smw + XS_W;

    const int b    = blockIdx.x >> 3;
    const int m0   = (blockIdx.x & 7) * 128;
    const size_t row0 = (size_t)blockIdx.x * 128;
    const int tid  = threadIdx.x;
    const int wid  = tid >> 5, lane = tid & 31;
    const int g = lane >> 2, t = lane & 3;
    const int l15 = lane & 15, lq = lane >> 4;
    const int wm1 = (wid >> 1) * 32, wn1 = (wid & 1) * 32;

    // ================= phase 1: edges tile = H[b] tile @ ori[b], kc=64 ======
    {
        const float* Hb   = H   + (size_t)b * EE * NN_;
        const float* orib = ori + (size_t)b * NN_ * DD;

        float acc[2][4][4];
#pragma unroll
        for (int mi = 0; mi < 2; mi++)
#pragma unroll
            for (int ni = 0; ni < 4; ni++)
#pragma unroll
                for (int jj = 0; jj < 4; jj++) acc[mi][ni][jj] = 0.f;

        const int br = tid >> 4, bcq = tid & 15;

        const uint32_t smP1 = sm_u32(region);
        const uint32_t offA = ((wm1 + l15) * K1_AW + 4 * lq) * 4;

        float4 ra[8], rb[4];
#pragma unroll
        for (int p = 0; p < 8; p++) {
            int f = tid + p * 256;
            ra[p] = *(const float4*)(Hb + (size_t)(m0 + (f >> 4)) * NN_ + (f & 15) * 4);
        }
#pragma unroll
        for (int q = 0; q < 2; q++) {
            int r = br + 16 * q;
            rb[2 * q]     = *(const float4*)(orib + (size_t)(2 * r) * DD + bcq * 4);
            rb[2 * q + 1] = *(const float4*)(orib + (size_t)(2 * r + 1) * DD + bcq * 4);
        }
        {
            uint32_t* A0 = region; uint32_t* B0 = region + K1_ASZ;
#pragma unroll
            for (int p = 0; p < 8; p++) {
                int f = tid + p * 256;
                uint2 w; w.x = h2(ra[p].x, ra[p].y); w.y = h2(ra[p].z, ra[p].w);
                *(uint2*)&A0[(f >> 4) * K1_AW + (f & 15) * 2] = w;
            }
#pragma unroll
            for (int q = 0; q < 2; q++) {
                int r = br + 16 * q;
                uint4 w;
                w.x = h2(rb[2 * q].x, rb[2 * q + 1].x);
                w.y = h2(rb[2 * q].y, rb[2 * q + 1].y);
                w.z = h2(rb[2 * q].z, rb[2 * q + 1].z);
                w.w = h2(rb[2 * q].w, rb[2 * q + 1].w);
                *(uint4*)&B0[r * K1_BW + bcq * 4] = w;
            }
        }
        __syncthreads();

        int buf = 0;
        for (int k0 = 0; k0 < NN_; k0 += 64) {
            const int kn = k0 + 64;
            if (kn < NN_) {
#pragma unroll
                for (int p = 0; p < 8; p++) {
                    int f = tid + p * 256;
                    ra[p] = *(const float4*)(Hb + (size_t)(m0 + (f >> 4)) * NN_ + kn + (f & 15) * 4);
                }
#pragma unroll
                for (int q = 0; q < 2; q++) {
                    int r = br + 16 * q;
                    rb[2 * q]     = *(const float4*)(orib + (size_t)(kn + 2 * r) * DD + bcq * 4);
                    rb[2 * q + 1] = *(const float4*)(orib + (size_t)(kn + 2 * r + 1) * DD + bcq * 4);
                }
            }
            const uint32_t abase = smP1 + (uint32_t)(buf * (K1_BUF * 4));
            const uint32_t* B_ = region + buf * K1_BUF + K1_ASZ;
#pragma unroll
            for (int kk = 0; kk < 4; kk++) {
                uint32_t a0[4], a1[4], bf[4][2];
                ldsm4(a0[0], a0[1], a0[2], a0[3], abase + offA + kk * 32);
                ldsm4(a1[0], a1[1], a1[2], a1[3], abase + offA + 2304 + kk * 32);
#pragma unroll
                for (int ni = 0; ni < 4; ni++) {
                    bf[ni][0] = B_[(8 * kk + t) * K1_BW + wn1 + 8 * ni + g];
                    bf[ni][1] = B_[(8 * kk + t + 4) * K1_BW + wn1 + 8 * ni + g];
                }
#pragma unroll
                for (int ni = 0; ni < 4; ni++) {
                    mma16(acc[0][ni], a0[0], a0[1], a0[2], a0[3], bf[ni][0], bf[ni][1]);
                    mma16(acc[1][ni], a1[0], a1[1], a1[2], a1[3], bf[ni][0], bf[ni][1]);
                }
            }
            if (kn < NN_) {
                uint32_t* An = region + (buf ^ 1) * K1_BUF;
                uint32_t* Bn = An + K1_ASZ;
#pragma unroll
                for (int p = 0; p < 8; p++) {
                    int f = tid + p * 256;
                    uint2 w; w.x = h2(ra[p].x, ra[p].y); w.y = h2(ra[p].z, ra[p].w);
                    *(uint2*)&An[(f >> 4) * K1_AW + (f & 15) * 2] = w;
                }
#pragma unroll
                for (int q = 0; q < 2; q++) {
                    int r = br + 16 * q;
                    uint4 w;
                    w.x = h2(rb[2 * q].x, rb[2 * q + 1].x);
                    w.y = h2(rb[2 * q].y, rb[2 * q + 1].y);
                    w.z = h2(rb[2 * q].z, rb[2 * q + 1].z);
                    w.w = h2(rb[2 * q].w, rb[2 * q + 1].w);
                    *(uint4*)&Bn[r * K1_BW + bcq * 4] = w;
                }
            }
            __syncthreads();
            buf ^= 1;
        }

        // epilogue: pack acc -> Xs
#pragma unroll
        for (int mi = 0; mi < 2; mi++)
#pragma unroll
            for (int ni = 0; ni < 4; ni++) {
                int r1 = wm1 + 16 * mi + g, r2 = r1 + 8;
                int cw = (wn1 >> 1) + 4 * ni + t;
                Xs[r1 * 36 + cw] = h2(acc[mi][ni][0], acc[mi][ni][1]);
                Xs[r2 * 36 + cw] = h2(acc[mi][ni][2], acc[mi][ni][3]);
            }
    }
    // ================= phase 2 setup ========================================
    uint32_t* W1s = region;
    uint32_t* W2s = region + 2 * W1_PW;
    float* wds = (float*)(W2s + 2 * W2_PW);
    float* b1s = wds + 640;
    float* b2s = b1s + 256;

    const int wm2 = wid * 16;

    for (int f = tid; f < 640; f += 256) wds[f] = ed[row0 * TT + f];
    stage_w(W1, W2, b1, b2, 0, 0, W1s, W2s, b1s, b2s, tid);
    __syncthreads();

    const uint32_t smX = sm_u32(Xs);
    const uint32_t offXA = ((wm2 + l15) * 36 + 4 * lq) * 4;
    uint32_t xa[4][4];
#pragma unroll
    for (int kc = 0; kc < 4; kc++)
        ldsm4(xa[kc][0], xa[kc][1], xa[kc][2], xa[kc][3], smX + offXA + kc * 32);

    float Y[8][4];
#pragma unroll
    for (int ni = 0; ni < 8; ni++)
#pragma unroll
        for (int jj = 0; jj < 4; jj++) Y[ni][jj] = 0.f;

    for (int et = 0; et < TT; et++) {
        const int pb = et & 1;
        if (et + 1 < TT)
            stage_w(W1, W2, b1, b2, et + 1, pb ^ 1, W1s, W2s, b1s, b2s, tid);

        const uint32_t* W1c = W1s + pb * W1_PW;
        const uint32_t* W2c = W2s + pb * W2_PW;

        float acc2[8][4];
#pragma unroll
        for (int ni = 0; ni < 8; ni++)
#pragma unroll
            for (int jj = 0; jj < 4; jj++) acc2[ni][jj] = 0.f;

#pragma unroll
        for (int s = 0; s < 8; s++) {
            float h0a[4] = {0.f, 0.f, 0.f, 0.f};
            float h1a[4] = {0.f, 0.f, 0.f, 0.f};
#pragma unroll
            for (int kc = 0; kc < 4; kc++) {
                uint32_t b00 = W1c[(8 * kc + t) * 136 + 16 * s + g];
                uint32_t b01 = W1c[(8 * kc + t + 4) * 136 + 16 * s + g];
                uint32_t b10 = W1c[(8 * kc + t) * 136 + 16 * s + 8 + g];
                uint32_t b11 = W1c[(8 * kc + t + 4) * 136 + 16 * s + 8 + g];
                mma16(h0a, xa[kc][0], xa[kc][1], xa[kc][2], xa[kc][3], b00, b01);
                mma16(h1a, xa[kc][0], xa[kc][1], xa[kc][2], xa[kc][3], b10, b11);
            }
            float bx0 = b1s[pb * 128 + 16 * s + 2 * t];
            float by0 = b1s[pb * 128 + 16 * s + 2 * t + 1];
            float bx1 = b1s[pb * 128 + 16 * s + 8 + 2 * t];
            float by1 = b1s[pb * 128 + 16 * s + 8 + 2 * t + 1];
            uint32_t af0 = h2(fmaxf(h0a[0] + bx0, 0.f), fmaxf(h0a[1] + by0, 0.f));
            uint32_t af1 = h2(fmaxf(h0a[2] + bx0, 0.f), fmaxf(h0a[3] + by0, 0.f));
            uint32_t af2 = h2(fmaxf(h1a[0] + bx1, 0.f), fmaxf(h1a[1] + by1, 0.f));
            uint32_t af3 = h2(fmaxf(h1a[2] + bx1, 0.f), fmaxf(h1a[3] + by1, 0.f));
#pragma unroll
            for (int ni = 0; ni < 8; ni++) {
                uint32_t b0 = W2c[(8 * s + t) * 72 + 8 * ni + g];
                uint32_t b1v = W2c[(8 * s + t + 4) * 72 + 8 * ni + g];
                mma16(acc2[ni], af0, af1, af2, af3, b0, b1v);
            }
        }
        float wA = wds[(wm2 + g) * TT + et];
        float wB = wds[(wm2 + 8 + g) * TT + et];
#pragma unroll
        for (int ni = 0; ni < 8; ni++) {
            int c = 8 * ni + 2 * t;
            float bx = b2s[pb * 64 + c], by = b2s[pb * 64 + c + 1];
            Y[ni][0] += wA * (acc2[ni][0] + bx);
            Y[ni][1] += wA * (acc2[ni][1] + by);
            Y[ni][2] += wB * (acc2[ni][2] + bx);
            Y[ni][3] += wB * (acc2[ni][3] + by);
        }
        __syncthreads();
    }

    // epilogue -> g_efh
    {
        int r1 = (int)row0 + wm2 + g, r2 = r1 + 8;
#pragma unroll
        for (int ni = 0; ni < 8; ni++) {
            g_efh[(size_t)r1 * 32 + 4 * ni + t] = h2(Y[ni][0], Y[ni][1]);
            g_efh[(size_t)r2 * 32 + 4 * ni + t] = h2(Y[ni][2], Y[ni][3]);
        }
    }

    // ori concat copy (moved from K3): CTA (b, tile) copies 64 node rows
    {
        const int n0 = (blockIdx.x & 7) * 64;
        const float* orib = ori + (size_t)b * NN_ * DD;
        float*       outb = out + (size_t)b * NN_ * (2 * DD);
#pragma unroll
        for (int p = 0; p < 4; p++) {
            int f = tid + p * 256;
            int r = f >> 4, cq = f & 15;
            float4 v = *(const float4*)(orib + (size_t)(n0 + r) * DD + cq * 4);
            *(float4*)(outb + (size_t)(n0 + r) * (2 * DD) + DD + cq * 4) = v;
        }
    }
}

// ---------------------------------------------------------------------------
// K3: node_agg = H^T @ ef only (concat moved to fused).
// Round-10 config: m-tile 64, e-chunk 64, 512 CTAs.
// ---------------------------------------------------------------------------
#define K3_HW 72
#define K3_BW 72
#define K3_HSZ (32 * K3_HW)
#define K3_BSZ (32 * K3_BW)
#define K3_BUF (K3_HSZ + K3_BSZ)
#define K3_SMEM_BYTES (2 * K3_BUF * 4)

__global__ __launch_bounds__(256) void k3_out(const float* __restrict__ H,
                                              float* __restrict__ out) {
    extern __shared__ uint32_t sw3[];

    const int b   = blockIdx.y;
    const int n0  = blockIdx.x * 64;
    const int tid = threadIdx.x;
    const int wid = tid >> 5, lane = tid & 31;
    const int g = lane >> 2, t = lane & 3;
    const int wm = (wid >> 1) * 16, wn = (wid & 1) * 32;

    const float* Hb = H + (size_t)b * EE * NN_;
    const uint32_t* efb = g_efh + (size_t)b * EE * 32;

    float acc[4][4];
#pragma unroll
    for (int ni = 0; ni < 4; ni++)
#pragma unroll
        for (int jj = 0; jj < 4; jj++) acc[ni][jj] = 0.f;

    const int hr = tid >> 4, hcq = tid & 15;   // 2 kpair rows per thread

    float4 ha[4];
    uint2 eb[4];
#pragma unroll
    for (int q = 0; q < 2; q++) {
        int r = hr + 16 * q;
        ha[2 * q]     = *(const float4*)(Hb + (size_t)(2 * r) * NN_ + n0 + hcq * 4);
        ha[2 * q + 1] = *(const float4*)(Hb + (size_t)(2 * r + 1) * NN_ + n0 + hcq * 4);
        eb[2 * q]     = *(const uint2*)&efb[(size_t)(2 * r) * 32 + hcq * 2];
        eb[2 * q + 1] = *(const uint2*)&efb[(size_t)(2 * r + 1) * 32 + hcq * 2];
    }
    {
        uint32_t* Hp = sw3; uint32_t* Bp = sw3 + K3_HSZ;
#pragma unroll
        for (int q = 0; q < 2; q++) {
            int r = hr + 16 * q;
            uint4 wh;
            wh.x = h2(ha[2 * q].x, ha[2 * q + 1].x);
            wh.y = h2(ha[2 * q].y, ha[2 * q + 1].y);
            wh.z = h2(ha[2 * q].z, ha[2 * q + 1].z);
            wh.w = h2(ha[2 * q].w, ha[2 * q + 1].w);
            *(uint4*)&Hp[r * K3_HW + hcq * 4] = wh;
            uint4 wb;
            wb.x = __byte_perm(eb[2 * q].x, eb[2 * q + 1].x, 0x5410);
            wb.y = __byte_perm(eb[2 * q].x, eb[2 * q + 1].x, 0x7632);
            wb.z = __byte_perm(eb[2 * q].y, eb[2 * q + 1].y, 0x5410);
            wb.w = __byte_perm(eb[2 * q].y, eb[2 * q + 1].y, 0x7632);
            *(uint4*)&Bp[r * K3_BW + hcq * 4] = wb;
        }
    }
    __syncthreads();

    int buf = 0;
    for (int e0 = 0; e0 < EE; e0 += 64) {
        const int en = e0 + 64;
        if (en < EE) {
#pragma unroll
            for (int q = 0; q < 2; q++) {
                int r = hr + 16 * q;
                ha[2 * q]     = *(const float4*)(Hb + (size_t)(en + 2 * r) * NN_ + n0 + hcq * 4);
                ha[2 * q + 1] = *(const float4*)(Hb + (size_t)(en + 2 * r + 1) * NN_ + n0 + hcq * 4);
                eb[2 * q]     = *(const uint2*)&efb[(size_t)(en + 2 * r) * 32 + hcq * 2];
                eb[2 * q + 1] = *(const uint2*)&efb[(size_t)(en + 2 * r + 1) * 32 + hcq * 2];
            }
        }
        const uint32_t* Hp = sw3 + buf * K3_BUF;
        const uint32_t* Bp = Hp + K3_HSZ;
#pragma unroll
        for (int kk = 0; kk < 4; kk++) {
            uint32_t a[4], bf[4][2];
            a[0] = Hp[(8 * kk + t) * K3_HW + wm + g];
            a[1] = Hp[(8 * kk + t) * K3_HW + wm + 8 + g];
            a[2] = Hp[(8 * kk + t + 4) * K3_HW + wm + g];
            a[3] = Hp[(8 * kk + t + 4) * K3_HW + wm + 8 + g];
#pragma unroll
            for (int ni = 0; ni < 4; ni++) {
                bf[ni][0] = Bp[(8 * kk + t) * K3_BW + wn + 8 * ni + g];
                bf[ni][1] = Bp[(8 * kk + t + 4) * K3_BW + wn + 8 * ni + g];
            }
#pragma unroll
            for (int ni = 0; ni < 4; ni++)
                mma16(acc[ni], a[0], a[1], a[2], a[3], bf[ni][0], bf[ni][1]);
        }
        if (en < EE) {
            uint32_t* Hn = sw3 + (buf ^ 1) * K3_BUF;
            uint32_t* Bn = Hn + K3_HSZ;
#pragma unroll
            for (int q = 0; q < 2; q++) {
                int r = hr + 16 * q;
                uint4 wh;
                wh.x = h2(ha[2 * q].x, ha[2 * q + 1].x);
                wh.y = h2(ha[2 * q].y, ha[2 * q + 1].y);
                wh.z = h2(ha[2 * q].z, ha[2 * q + 1].z);
                wh.w = h2(ha[2 * q].w, ha[2 * q + 1].w);
                *(uint4*)&Hn[r * K3_HW + hcq * 4] = wh;
                uint4 wb;
                wb.x = __byte_perm(eb[2 * q].x, eb[2 * q + 1].x, 0x5410);
                wb.y = __byte_perm(eb[2 * q].x, eb[2 * q + 1].x, 0x7632);
                wb.z = __byte_perm(eb[2 * q].y, eb[2 * q + 1].y, 0x5410);
                wb.w = __byte_perm(eb[2 * q].y, eb[2 * q + 1].y, 0x7632);
                *(uint4*)&Bn[r * K3_BW + hcq * 4] = wb;
            }
        }
        __syncthreads();
        buf ^= 1;
    }

    float* outb = out + (size_t)b * NN_ * (2 * DD);
#pragma unroll
    for (int ni = 0; ni < 4; ni++) {
        int r1 = n0 + wm + g, r2 = r1 + 8;
        int c  = wn + 8 * ni + 2 * t;
        *(float2*)(outb + (size_t)r1 * (2 * DD) + c) =
            make_float2(acc[ni][0], acc[ni][1]);
        *(float2*)(outb + (size_t)r2 * (2 * DD) + c) =
            make_float2(acc[ni][2], acc[ni][3]);
    }
}

// ---------------------------------------------------------------------------
extern "C" void kernel_launch(void* const* d_in, const int* in_sizes, int n_in,
                              void* d_out, int out_size) {
    const float* ed  = (const float*)d_in[0];
    const float* H   = (const float*)d_in[1];
    const float* ori = (const float*)d_in[2];
    const float* W1  = (const float*)d_in[3];
    const float* b1  = (const float*)d_in[4];
    const float* W2  = (const float*)d_in[5];
    const float* b2  = (const float*)d_in[6];
    float* out = (float*)d_out;

    cudaFuncSetAttribute(kf_fused, cudaFuncAttributeMaxDynamicSharedMemorySize,
                         KF_SMEM_BYTES);

    kf_fused<<<(BB * EE) / 128, 256, KF_SMEM_BYTES>>>(H, ori, ed, W1, b1, W2, b2, out);

    dim3 g3(NN_ / 64, BB);
    k3_out<<<g3, 256, K3_SMEM_BYTES>>>(H, out);
}

// round 16
// speedup vs baseline: 1.1881x; 1.0754x over previous
#include <cuda_runtime.h>
#include <cuda_fp16.h>
#include <cstdint>

#define BB 64
#define EE 1024
#define NN_ 512
#define DD 64
#define HH 128
#define TT 5

// fp16-packed scratch (word = half2)
__device__ uint32_t g_efh[BB * EE * (DD / 2)];   // 8 MB: edge_feature
__device__ uint32_t g_W1h[TT * 32 * 128];        // packed W1: [t][kpair r][h]
__device__ uint32_t g_W2h[TT * 64 * 64];         // packed W2: [t][kpair r][d]

// ---------------------------------------------------------------------------
// helpers
// ---------------------------------------------------------------------------
__device__ __forceinline__ uint32_t h2(float lo, float hi) {
    __half2 h = __floats2half2_rn(lo, hi);
    return *reinterpret_cast<uint32_t*>(&h);
}
__device__ __forceinline__ uint32_t sm_u32(const void* p) {
    return (uint32_t)__cvta_generic_to_shared(p);
}
__device__ __forceinline__ void ldsm4(uint32_t& r0, uint32_t& r1, uint32_t& r2,
                                      uint32_t& r3, uint32_t addr) {
    asm volatile("ldmatrix.sync.aligned.m8n8.x4.shared.b16 {%0,%1,%2,%3}, [%4];"
                 : "=r"(r0), "=r"(r1), "=r"(r2), "=r"(r3) : "r"(addr));
}
__device__ __forceinline__ void mma16(float* c, uint32_t a0, uint32_t a1,
                                      uint32_t a2, uint32_t a3,
                                      uint32_t b0, uint32_t b1) {
    asm volatile(
        "mma.sync.aligned.m16n8k16.row.col.f32.f16.f16.f32 "
        "{%0,%1,%2,%3}, {%4,%5,%6,%7}, {%8,%9}, {%0,%1,%2,%3};"
        : "+f"(c[0]), "+f"(c[1]), "+f"(c[2]), "+f"(c[3])
        : "r"(a0), "r"(a1), "r"(a2), "r"(a3), "r"(b0), "r"(b1));
}

// ---------------------------------------------------------------------------
// k0: one-time fp32 -> packed fp16 weight conversion (shared by all CTAs)
// ---------------------------------------------------------------------------
__global__ __launch_bounds__(256) void k0_pack(const float* __restrict__ W1,
                                               const float* __restrict__ W2) {
    int i = blockIdx.x * 256 + threadIdx.x;
    if (i < TT * 32 * 128) {   // W1 word: t, kpair r (d), col h
        int t = i / 4096, rem = i % 4096, r = rem >> 7, hcol = rem & 127;
        const float* w1 = W1 + (size_t)t * DD * HH;
        g_W1h[i] = h2(w1[(size_t)(2 * r) * HH + hcol],
                      w1[(size_t)(2 * r + 1) * HH + hcol]);
    }
    if (i < TT * 64 * 64) {    // W2 word: t, kpair r (h), col d
        int t = i / 4096, rem = i % 4096, r = rem >> 6, dcol = rem & 63;
        const float* w2 = W2 + (size_t)t * HH * DD;
        g_W2h[i] = h2(w2[(size_t)(2 * r) * DD + dcol],
                      w2[(size_t)(2 * r + 1) * DD + dcol]);
    }
}

// ---------------------------------------------------------------------------
// KF: fused (edges = H @ ori) + per-type MLP mixture + ori concat copy.
// Phase 2: packed-weight raw-copy staging + mixture folded into GEMM2 A-op.
// ---------------------------------------------------------------------------
#define XS_W    (128 * 36)
#define K1_AW   36
#define K1_BW   72
#define K1_ASZ  (128 * K1_AW)    // 4608 w
#define K1_BSZ  (32 * K1_BW)     // 2304 w
#define K1_BUF  (K1_ASZ + K1_BSZ)
#define W1_PW   (32 * 136)       // one parity: [32 kp(d)][136w n(h)]
#define W2_PW   (64 * 72)        // one parity: [64 kp(h)][72w n(d)]
#define K2_REGION_W (2 * W1_PW + 2 * W2_PW + 640 + 640 + 320)
#define KF_REGION_W (K2_REGION_W > 2 * K1_BUF ? K2_REGION_W : 2 * K1_BUF)
#define KF_SMEM_BYTES ((XS_W + KF_REGION_W) * 4)

// raw copy of pre-packed weights into smem parity buffers
__device__ __forceinline__ void stage_w(int tt, int par, uint32_t* W1s,
                                        uint32_t* W2s, int tid) {
    const uint4* w1 = (const uint4*)(g_W1h + (size_t)tt * 4096);
    const uint4* w2 = (const uint4*)(g_W2h + (size_t)tt * 4096);
#pragma unroll
    for (int p = 0; p < 4; p++) {
        int f4 = tid + p * 256;     // uint4 index 0..1023
        {   // W1: word = f4*4 -> r = f4>>5, c = (f4&31)*4
            *(uint4*)&W1s[par * W1_PW + (f4 >> 5) * 136 + (f4 & 31) * 4] = w1[f4];
        }
        {   // W2: r = f4>>4, c = (f4&15)*4
            *(uint4*)&W2s[par * W2_PW + (f4 >> 4) * 72 + (f4 & 15) * 4] = w2[f4];
        }
    }
}

__global__ __launch_bounds__(256, 2) void kf_fused(
    const float* __restrict__ H,  const float* __restrict__ ori,
    const float* __restrict__ ed, const float* __restrict__ b1,
    const float* __restrict__ b2, float* __restrict__ out) {
    extern __shared__ uint32_t smw[];
    uint32_t* Xs     = smw;          // [128][36w] persistent
    uint32_t* region = smw + XS_W;

    const int b    = blockIdx.x >> 3;
    const int m0   = (blockIdx.x & 7) * 128;
    const size_t row0 = (size_t)blockIdx.x * 128;
    const int tid  = threadIdx.x;
    const int wid  = tid >> 5, lane = tid & 31;
    const int g = lane >> 2, t = lane & 3;
    const int l15 = lane & 15, lq = lane >> 4;
    const int wm1 = (wid >> 1) * 32, wn1 = (wid & 1) * 32;

    // ================= phase 1: edges tile = H[b] tile @ ori[b], kc=64 ======
    {
        const float* Hb   = H   + (size_t)b * EE * NN_;
        const float* orib = ori + (size_t)b * NN_ * DD;

        float acc[2][4][4];
#pragma unroll
        for (int mi = 0; mi < 2; mi++)
#pragma unroll
            for (int ni = 0; ni < 4; ni++)
#pragma unroll
                for (int jj = 0; jj < 4; jj++) acc[mi][ni][jj] = 0.f;

        const int br = tid >> 4, bcq = tid & 15;

        const uint32_t smP1 = sm_u32(region);
        const uint32_t offA = ((wm1 + l15) * K1_AW + 4 * lq) * 4;

        float4 ra[8], rb[4];
#pragma unroll
        for (int p = 0; p < 8; p++) {
            int f = tid + p * 256;
            ra[p] = *(const float4*)(Hb + (size_t)(m0 + (f >> 4)) * NN_ + (f & 15) * 4);
        }
#pragma unroll
        for (int q = 0; q < 2; q++) {
            int r = br + 16 * q;
            rb[2 * q]     = *(const float4*)(orib + (size_t)(2 * r) * DD + bcq * 4);
            rb[2 * q + 1] = *(const float4*)(orib + (size_t)(2 * r + 1) * DD + bcq * 4);
        }
        {
            uint32_t* A0 = region; uint32_t* B0 = region + K1_ASZ;
#pragma unroll
            for (int p = 0; p < 8; p++) {
                int f = tid + p * 256;
                uint2 w; w.x = h2(ra[p].x, ra[p].y); w.y = h2(ra[p].z, ra[p].w);
                *(uint2*)&A0[(f >> 4) * K1_AW + (f & 15) * 2] = w;
            }
#pragma unroll
            for (int q = 0; q < 2; q++) {
                int r = br + 16 * q;
                uint4 w;
                w.x = h2(rb[2 * q].x, rb[2 * q + 1].x);
                w.y = h2(rb[2 * q].y, rb[2 * q + 1].y);
                w.z = h2(rb[2 * q].z, rb[2 * q + 1].z);
                w.w = h2(rb[2 * q].w, rb[2 * q + 1].w);
                *(uint4*)&B0[r * K1_BW + bcq * 4] = w;
            }
        }
        __syncthreads();

        int buf = 0;
        for (int k0 = 0; k0 < NN_; k0 += 64) {
            const int kn = k0 + 64;
            if (kn < NN_) {
#pragma unroll
                for (int p = 0; p < 8; p++) {
                    int f = tid + p * 256;
                    ra[p] = *(const float4*)(Hb + (size_t)(m0 + (f >> 4)) * NN_ + kn + (f & 15) * 4);
                }
#pragma unroll
                for (int q = 0; q < 2; q++) {
                    int r = br + 16 * q;
                    rb[2 * q]     = *(const float4*)(orib + (size_t)(kn + 2 * r) * DD + bcq * 4);
                    rb[2 * q + 1] = *(const float4*)(orib + (size_t)(kn + 2 * r + 1) * DD + bcq * 4);
                }
            }
            const uint32_t abase = smP1 + (uint32_t)(buf * (K1_BUF * 4));
            const uint32_t* B_ = region + buf * K1_BUF + K1_ASZ;
#pragma unroll
            for (int kk = 0; kk < 4; kk++) {
                uint32_t a0[4], a1[4], bf[4][2];
                ldsm4(a0[0], a0[1], a0[2], a0[3], abase + offA + kk * 32);
                ldsm4(a1[0], a1[1], a1[2], a1[3], abase + offA + 2304 + kk * 32);
#pragma unroll
                for (int ni = 0; ni < 4; ni++) {
                    bf[ni][0] = B_[(8 * kk + t) * K1_BW + wn1 + 8 * ni + g];
                    bf[ni][1] = B_[(8 * kk + t + 4) * K1_BW + wn1 + 8 * ni + g];
                }
#pragma unroll
                for (int ni = 0; ni < 4; ni++) {
                    mma16(acc[0][ni], a0[0], a0[1], a0[2], a0[3], bf[ni][0], bf[ni][1]);
                    mma16(acc[1][ni], a1[0], a1[1], a1[2], a1[3], bf[ni][0], bf[ni][1]);
                }
            }
            if (kn < NN_) {
                uint32_t* An = region + (buf ^ 1) * K1_BUF;
                uint32_t* Bn = An + K1_ASZ;
#pragma unroll
                for (int p = 0; p < 8; p++) {
                    int f = tid + p * 256;
                    uint2 w; w.x = h2(ra[p].x, ra[p].y); w.y = h2(ra[p].z, ra[p].w);
                    *(uint2*)&An[(f >> 4) * K1_AW + (f & 15) * 2] = w;
                }
#pragma unroll
                for (int q = 0; q < 2; q++) {
                    int r = br + 16 * q;
                    uint4 w;
                    w.x = h2(rb[2 * q].x, rb[2 * q + 1].x);
                    w.y = h2(rb[2 * q].y, rb[2 * q + 1].y);
                    w.z = h2(rb[2 * q].z, rb[2 * q + 1].z);
                    w.w = h2(rb[2 * q].w, rb[2 * q + 1].w);
                    *(uint4*)&Bn[r * K1_BW + bcq * 4] = w;
                }
            }
            __syncthreads();
            buf ^= 1;
        }

        // epilogue: pack acc -> Xs
#pragma unroll
        for (int mi = 0; mi < 2; mi++)
#pragma unroll
            for (int ni = 0; ni < 4; ni++) {
                int r1 = wm1 + 16 * mi + g, r2 = r1 + 8;
                int cw = (wn1 >> 1) + 4 * ni + t;
                Xs[r1 * 36 + cw] = h2(acc[mi][ni][0], acc[mi][ni][1]);
                Xs[r2 * 36 + cw] = h2(acc[mi][ni][2], acc[mi][ni][3]);
            }
    }
    // ================= phase 2 setup ========================================
    uint32_t* W1s = region;                    // 2 parity x [32][136w]
    uint32_t* W2s = region + 2 * W1_PW;        // 2 parity x [64][72w]
    float* wds = (float*)(W2s + 2 * W2_PW);    // [128][5]
    float* b1a = wds + 640;                    // [5][128]
    float* b2a = b1a + 640;                    // [5][64]

    const int wm2 = wid * 16;

    for (int f = tid; f < 640; f += 256) wds[f] = ed[row0 * TT + f];
    for (int f = tid; f < TT * HH; f += 256) b1a[f] = b1[f];
    for (int f = tid; f < TT * DD; f += 256) b2a[f] = b2[f];
    stage_w(0, 0, W1s, W2s, tid);
    __syncthreads();

    const uint32_t smX = sm_u32(Xs);
    const uint32_t offXA = ((wm2 + l15) * 36 + 4 * lq) * 4;
    uint32_t xa[4][4];
#pragma unroll
    for (int kc = 0; kc < 4; kc++)
        ldsm4(xa[kc][0], xa[kc][1], xa[kc][2], xa[kc][3], smX + offXA + kc * 32);

    float Y[8][4];
#pragma unroll
    for (int ni = 0; ni < 8; ni++)
#pragma unroll
        for (int jj = 0; jj < 4; jj++) Y[ni][jj] = 0.f;

    const int r1 = wm2 + g, r2 = wm2 + 8 + g;   // rows this thread owns

    // ================= phase 2: 5-type MLP mixture (folded) =================
    for (int et = 0; et < TT; et++) {
        const int pb = et & 1;
        if (et + 1 < TT) stage_w(et + 1, pb ^ 1, W1s, W2s, tid);

        const uint32_t* W1c = W1s + pb * W1_PW;
        const uint32_t* W2c = W2s + pb * W2_PW;

        const float wA = wds[r1 * TT + et];
        const float wB = wds[r2 * TT + et];

#pragma unroll
        for (int s = 0; s < 8; s++) {
            float h0a[4] = {0.f, 0.f, 0.f, 0.f};
            float h1a[4] = {0.f, 0.f, 0.f, 0.f};
#pragma unroll
            for (int kc = 0; kc < 4; kc++) {
                uint32_t b00 = W1c[(8 * kc + t) * 136 + 16 * s + g];
                uint32_t b01 = W1c[(8 * kc + t + 4) * 136 + 16 * s + g];
                uint32_t b10 = W1c[(8 * kc + t) * 136 + 16 * s + 8 + g];
                uint32_t b11 = W1c[(8 * kc + t + 4) * 136 + 16 * s + 8 + g];
                mma16(h0a, xa[kc][0], xa[kc][1], xa[kc][2], xa[kc][3], b00, b01);
                mma16(h1a, xa[kc][0], xa[kc][1], xa[kc][2], xa[kc][3], b10, b11);
            }
            float bx0 = b1a[et * HH + 16 * s + 2 * t];
            float by0 = b1a[et * HH + 16 * s + 2 * t + 1];
            float bx1 = b1a[et * HH + 16 * s + 8 + 2 * t];
            float by1 = b1a[et * HH + 16 * s + 8 + 2 * t + 1];
            // relu + mixture-weight scaling folded into the fp16 pack
            uint32_t af0 = h2(wA * fmaxf(h0a[0] + bx0, 0.f), wA * fmaxf(h0a[1] + by0, 0.f));
            uint32_t af1 = h2(wB * fmaxf(h0a[2] + bx0, 0.f), wB * fmaxf(h0a[3] + by0, 0.f));
            uint32_t af2 = h2(wA * fmaxf(h1a[0] + bx1, 0.f), wA * fmaxf(h1a[1] + by1, 0.f));
            uint32_t af3 = h2(wB * fmaxf(h1a[2] + bx1, 0.f), wB * fmaxf(h1a[3] + by1, 0.f));
#pragma unroll
            for (int ni = 0; ni < 8; ni++) {
                uint32_t b0 = W2c[(8 * s + t) * 72 + 8 * ni + g];
                uint32_t b1v = W2c[(8 * s + t + 4) * 72 + 8 * ni + g];
                mma16(Y[ni], af0, af1, af2, af3, b0, b1v);   // accumulate into Y
            }
        }
        __syncthreads();   // parity pb reads done; next stage may overwrite
    }

    // closed-form bias term: Y[r][c] += sum_t w[r][t] * b2[t][c]
    {
        float wv1[TT], wv2[TT];
#pragma unroll
        for (int t5 = 0; t5 < TT; t5++) {
            wv1[t5] = wds[r1 * TT + t5];
            wv2[t5] = wds[r2 * TT + t5];
        }
#pragma unroll
        for (int ni = 0; ni < 8; ni++) {
            int c = 8 * ni + 2 * t;
            float s0 = 0.f, s1 = 0.f, s2 = 0.f, s3 = 0.f;
#pragma unroll
            for (int t5 = 0; t5 < TT; t5++) {
                float bx = b2a[t5 * DD + c], by = b2a[t5 * DD + c + 1];
                s0 += wv1[t5] * bx; s1 += wv1[t5] * by;
                s2 += wv2[t5] * bx; s3 += wv2[t5] * by;
            }
            Y[ni][0] += s0; Y[ni][1] += s1;
            Y[ni][2] += s2; Y[ni][3] += s3;
        }
    }

    // epilogue -> g_efh
    {
        int gr1 = (int)row0 + r1, gr2 = (int)row0 + r2;
#pragma unroll
        for (int ni = 0; ni < 8; ni++) {
            g_efh[(size_t)gr1 * 32 + 4 * ni + t] = h2(Y[ni][0], Y[ni][1]);
            g_efh[(size_t)gr2 * 32 + 4 * ni + t] = h2(Y[ni][2], Y[ni][3]);
        }
    }

    // ori concat copy: CTA (b, tile) copies 64 node rows
    {
        const int n0 = (blockIdx.x & 7) * 64;
        const float* orib = ori + (size_t)b * NN_ * DD;
        float*       outb = out + (size_t)b * NN_ * (2 * DD);
#pragma unroll
        for (int p = 0; p < 4; p++) {
            int f = tid + p * 256;
            int r = f >> 4, cq = f & 15;
            float4 v = *(const float4*)(orib + (size_t)(n0 + r) * DD + cq * 4);
            *(float4*)(outb + (size_t)(n0 + r) * (2 * DD) + DD + cq * 4) = v;
        }
    }
}

// ---------------------------------------------------------------------------
// K3: node_agg = H^T @ ef (round-15 version, unchanged)
// ---------------------------------------------------------------------------
#define K3_HW 72
#define K3_BW 72
#define K3_HSZ (32 * K3_HW)
#define K3_BSZ (32 * K3_BW)
#define K3_BUF (K3_HSZ + K3_BSZ)
#define K3_SMEM_BYTES (2 * K3_BUF * 4)

__global__ __launch_bounds__(256) void k3_out(const float* __restrict__ H,
                                              float* __restrict__ out) {
    extern __shared__ uint32_t sw3[];

    const int b   = blockIdx.y;
    const int n0  = blockIdx.x * 64;
    const int tid = threadIdx.x;
    const int wid = tid >> 5, lane = tid & 31;
    const int g = lane >> 2, t = lane & 3;
    const int wm = (wid >> 1) * 16, wn = (wid & 1) * 32;

    const float* Hb = H + (size_t)b * EE * NN_;
    const uint32_t* efb = g_efh + (size_t)b * EE * 32;

    float acc[4][4];
#pragma unroll
    for (int ni = 0; ni < 4; ni++)
#pragma unroll
        for (int jj = 0; jj < 4; jj++) acc[ni][jj] = 0.f;

    const int hr = tid >> 4, hcq = tid & 15;

    float4 ha[4];
    uint2 eb[4];
#pragma unroll
    for (int q = 0; q < 2; q++) {
        int r = hr + 16 * q;
        ha[2 * q]     = *(const float4*)(Hb + (size_t)(2 * r) * NN_ + n0 + hcq * 4);
        ha[2 * q + 1] = *(const float4*)(Hb + (size_t)(2 * r + 1) * NN_ + n0 + hcq * 4);
        eb[2 * q]     = *(const uint2*)&efb[(size_t)(2 * r) * 32 + hcq * 2];
        eb[2 * q + 1] = *(const uint2*)&efb[(size_t)(2 * r + 1) * 32 + hcq * 2];
    }
    {
        uint32_t* Hp = sw3; uint32_t* Bp = sw3 + K3_HSZ;
#pragma unroll
        for (int q = 0; q < 2; q++) {
            int r = hr + 16 * q;
            uint4 wh;
            wh.x = h2(ha[2 * q].x, ha[2 * q + 1].x);
            wh.y = h2(ha[2 * q].y, ha[2 * q + 1].y);
            wh.z = h2(ha[2 * q].z, ha[2 * q + 1].z);
            wh.w = h2(ha[2 * q].w, ha[2 * q + 1].w);
            *(uint4*)&Hp[r * K3_HW + hcq * 4] = wh;
            uint4 wb;
            wb.x = __byte_perm(eb[2 * q].x, eb[2 * q + 1].x, 0x5410);
            wb.y = __byte_perm(eb[2 * q].x, eb[2 * q + 1].x, 0x7632);
            wb.z = __byte_perm(eb[2 * q].y, eb[2 * q + 1].y, 0x5410);
            wb.w = __byte_perm(eb[2 * q].y, eb[2 * q + 1].y, 0x7632);
            *(uint4*)&Bp[r * K3_BW + hcq * 4] = wb;
        }
    }
    __syncthreads();

    int buf = 0;
    for (int e0 = 0; e0 < EE; e0 += 64) {
        const int en = e0 + 64;
        if (en < EE) {
#pragma unroll
            for (int q = 0; q < 2; q++) {
                int r = hr + 16 * q;
                ha[2 * q]     = *(const float4*)(Hb + (size_t)(en + 2 * r) * NN_ + n0 + hcq * 4);
                ha[2 * q + 1] = *(const float4*)(Hb + (size_t)(en + 2 * r + 1) * NN_ + n0 + hcq * 4);
                eb[2 * q]     = *(const uint2*)&efb[(size_t)(en + 2 * r) * 32 + hcq * 2];
                eb[2 * q + 1] = *(const uint2*)&efb[(size_t)(en + 2 * r + 1) * 32 + hcq * 2];
            }
        }
        const uint32_t* Hp = sw3 + buf * K3_BUF;
        const uint32_t* Bp = Hp + K3_HSZ;
#pragma unroll
        for (int kk = 0; kk < 4; kk++) {
            uint32_t a[4], bf[4][2];
            a[0] = Hp[(8 * kk + t) * K3_HW + wm + g];
            a[1] = Hp[(8 * kk + t) * K3_HW + wm + 8 + g];
            a[2] = Hp[(8 * kk + t + 4) * K3_HW + wm + g];
            a[3] = Hp[(8 * kk + t + 4) * K3_HW + wm + 8 + g];
#pragma unroll
            for (int ni = 0; ni < 4; ni++) {
                bf[ni][0] = Bp[(8 * kk + t) * K3_BW + wn + 8 * ni + g];
                bf[ni][1] = Bp[(8 * kk + t + 4) * K3_BW + wn + 8 * ni + g];
            }
#pragma unroll
            for (int ni = 0; ni < 4; ni++)
                mma16(acc[ni], a[0], a[1], a[2], a[3], bf[ni][0], bf[ni][1]);
        }
        if (en < EE) {
            uint32_t* Hn = sw3 + (buf ^ 1) * K3_BUF;
            uint32_t* Bn = Hn + K3_HSZ;
#pragma unroll
            for (int q = 0; q < 2; q++) {
                int r = hr + 16 * q;
                uint4 wh;
                wh.x = h2(ha[2 * q].x, ha[2 * q + 1].x);
                wh.y = h2(ha[2 * q].y, ha[2 * q + 1].y);
                wh.z = h2(ha[2 * q].z, ha[2 * q + 1].z);
                wh.w = h2(ha[2 * q].w, ha[2 * q + 1].w);
                *(uint4*)&Hn[r * K3_HW + hcq * 4] = wh;
                uint4 wb;
                wb.x = __byte_perm(eb[2 * q].x, eb[2 * q + 1].x, 0x5410);
                wb.y = __byte_perm(eb[2 * q].x, eb[2 * q + 1].x, 0x7632);
                wb.z = __byte_perm(eb[2 * q].y, eb[2 * q + 1].y, 0x5410);
                wb.w = __byte_perm(eb[2 * q].y, eb[2 * q + 1].y, 0x7632);
                *(uint4*)&Bn[r * K3_BW + hcq * 4] = wb;
            }
        }
        __syncthreads();
        buf ^= 1;
    }

    float* outb = out + (size_t)b * NN_ * (2 * DD);
#pragma unroll
    for (int ni = 0; ni < 4; ni++) {
        int r1 = n0 + wm + g, r2 = r1 + 8;
        int c  = wn + 8 * ni + 2 * t;
        *(float2*)(outb + (size_t)r1 * (2 * DD) + c) =
            make_float2(acc[ni][0], acc[ni][1]);
        *(float2*)(outb + (size_t)r2 * (2 * DD) + c) =
            make_float2(acc[ni][2], acc[ni][3]);
    }
}

// ---------------------------------------------------------------------------
extern "C" void kernel_launch(void* const* d_in, const int* in_sizes, int n_in,
                              void* d_out, int out_size) {
    const float* ed  = (const float*)d_in[0];
    const float* H   = (const float*)d_in[1];
    const float* ori = (const float*)d_in[2];
    const float* W1  = (const float*)d_in[3];
    const float* b1  = (const float*)d_in[4];
    const float* W2  = (const float*)d_in[5];
    const float* b2  = (const float*)d_in[6];
    float* out = (float*)d_out;

    cudaFuncSetAttribute(kf_fused, cudaFuncAttributeMaxDynamicSharedMemorySize,
                         KF_SMEM_BYTES);

    k0_pack<<<80, 256>>>(W1, W2);

    kf_fused<<<(BB * EE) / 128, 256, KF_SMEM_BYTES>>>(H, ori, ed, b1, b2, out);

    dim3 g3(NN_ / 64, BB);
    k3_out<<<g3, 256, K3_SMEM_BYTES>>>(H, out);
}

// round 17
// speedup vs baseline: 1.2105x; 1.0188x over previous
#include <cuda_runtime.h>
#include <cuda_fp16.h>
#include <cstdint>

#define BB 64
#define EE 1024
#define NN_ 512
#define DD 64
#define HH 128
#define TT 5

// fp16-packed scratch (word = half2)
__device__ uint32_t g_efh[BB * EE * (DD / 2)];   // 8 MB: edge_feature
__device__ uint32_t g_W1h[TT * 128 * 32];        // packed W1 n-major: [t][h][dpair]
__device__ uint32_t g_W2h[TT * 64 * 64];         // packed W2 n-major: [t][d][hpair]

// ---------------------------------------------------------------------------
// helpers
// ---------------------------------------------------------------------------
__device__ __forceinline__ uint32_t h2(float lo, float hi) {
    __half2 h = __floats2half2_rn(lo, hi);
    return *reinterpret_cast<uint32_t*>(&h);
}
__device__ __forceinline__ uint32_t sm_u32(const void* p) {
    return (uint32_t)__cvta_generic_to_shared(p);
}
__device__ __forceinline__ void ldsm4(uint32_t& r0, uint32_t& r1, uint32_t& r2,
                                      uint32_t& r3, uint32_t addr) {
    asm volatile("ldmatrix.sync.aligned.m8n8.x4.shared.b16 {%0,%1,%2,%3}, [%4];"
                 : "=r"(r0), "=r"(r1), "=r"(r2), "=r"(r3) : "r"(addr));
}
__device__ __forceinline__ void mma16(float* c, uint32_t a0, uint32_t a1,
                                      uint32_t a2, uint32_t a3,
                                      uint32_t b0, uint32_t b1) {
    asm volatile(
        "mma.sync.aligned.m16n8k16.row.col.f32.f16.f16.f32 "
        "{%0,%1,%2,%3}, {%4,%5,%6,%7}, {%8,%9}, {%0,%1,%2,%3};"
        : "+f"(c[0]), "+f"(c[1]), "+f"(c[2]), "+f"(c[3])
        : "r"(a0), "r"(a1), "r"(a2), "r"(a3), "r"(b0), "r"(b1));
}

// ---------------------------------------------------------------------------
// k0: one-time fp32 -> packed fp16 weights, n-major layouts for LDSM B-frags
// ---------------------------------------------------------------------------
__global__ __launch_bounds__(256) void k0_pack(const float* __restrict__ W1,
                                               const float* __restrict__ W2) {
    int i = blockIdx.x * 256 + threadIdx.x;
    if (i < TT * 128 * 32) {   // W1 word: [t][h][dpair r]
        int t = i / 4096, rem = i % 4096, hcol = rem >> 5, r = rem & 31;
        const float* w1 = W1 + (size_t)t * DD * HH;
        g_W1h[i] = h2(w1[(size_t)(2 * r) * HH + hcol],
                      w1[(size_t)(2 * r + 1) * HH + hcol]);
    }
    if (i < TT * 64 * 64) {    // W2 word: [t][d][hpair r]
        int t = i / 4096, rem = i % 4096, dcol = rem >> 6, r = rem & 63;
        const float* w2 = W2 + (size_t)t * HH * DD;
        g_W2h[i] = h2(w2[(size_t)(2 * r) * DD + dcol],
                      w2[(size_t)(2 * r + 1) * DD + dcol]);
    }
}

// ---------------------------------------------------------------------------
// KF: fused (edges = H @ ori) + per-type MLP mixture + ori concat copy.
// Phase 2: n-major weight tiles, B-fragments via LDSM (round-6 proven map).
// ---------------------------------------------------------------------------
#define XS_W    (128 * 36)
#define K1_AW   36
#define K1_BW   72
#define K1_ASZ  (128 * K1_AW)    // 4608 w
#define K1_BSZ  (32 * K1_BW)     // 2304 w
#define K1_BUF  (K1_ASZ + K1_BSZ)
#define W1_PW   (128 * 36)       // one parity: [128 h][36w dpair]
#define W2_PW   (64 * 68)        // one parity: [64 d][68w hpair]
#define K2_REGION_W (2 * W1_PW + 2 * W2_PW + 640 + 640 + 320)
#define KF_REGION_W (K2_REGION_W > 2 * K1_BUF ? K2_REGION_W : 2 * K1_BUF)
#define KF_SMEM_BYTES ((XS_W + KF_REGION_W) * 4)

// raw copy of pre-packed weights into smem parity buffers
__device__ __forceinline__ void stage_w(int tt, int par, uint32_t* W1s,
                                        uint32_t* W2s, int tid) {
    const uint4* w1 = (const uint4*)(g_W1h + (size_t)tt * 4096);
    const uint4* w2 = (const uint4*)(g_W2h + (size_t)tt * 4096);
#pragma unroll
    for (int p = 0; p < 4; p++) {
        int f4 = tid + p * 256;     // uint4 index 0..1023
        {   // W1: row h = f4>>3, quad = f4&7
            *(uint4*)&W1s[par * W1_PW + (f4 >> 3) * 36 + (f4 & 7) * 4] = w1[f4];
        }
        {   // W2: row d = f4>>4, quad = f4&15
            *(uint4*)&W2s[par * W2_PW + (f4 >> 4) * 68 + (f4 & 15) * 4] = w2[f4];
        }
    }
}

__global__ __launch_bounds__(256, 2) void kf_fused(
    const float* __restrict__ H,  const float* __restrict__ ori,
    const float* __restrict__ ed, const float* __restrict__ b1,
    const float* __restrict__ b2, float* __restrict__ out) {
    extern __shared__ uint32_t smw[];
    uint32_t* Xs     = smw;          // [128][36w] persistent
    uint32_t* region = smw + XS_W;

    const int b    = blockIdx.x >> 3;
    const int m0   = (blockIdx.x & 7) * 128;
    const size_t row0 = (size_t)blockIdx.x * 128;
    const int tid  = threadIdx.x;
    const int wid  = tid >> 5, lane = tid & 31;
    const int g = lane >> 2, t = lane & 3;
    const int l15 = lane & 15, lq = lane >> 4;
    const int lh = (lane >> 3) & 1, lo = lane & 7;
    const int wm1 = (wid >> 1) * 32, wn1 = (wid & 1) * 32;

    // ================= phase 1: edges tile = H[b] tile @ ori[b], kc=64 ======
    {
        const float* Hb   = H   + (size_t)b * EE * NN_;
        const float* orib = ori + (size_t)b * NN_ * DD;

        float acc[2][4][4];
#pragma unroll
        for (int mi = 0; mi < 2; mi++)
#pragma unroll
            for (int ni = 0; ni < 4; ni++)
#pragma unroll
                for (int jj = 0; jj < 4; jj++) acc[mi][ni][jj] = 0.f;

        const int br = tid >> 4, bcq = tid & 15;

        const uint32_t smP1 = sm_u32(region);
        const uint32_t offA = ((wm1 + l15) * K1_AW + 4 * lq) * 4;

        float4 ra[8], rb[4];
#pragma unroll
        for (int p = 0; p < 8; p++) {
            int f = tid + p * 256;
            ra[p] = *(const float4*)(Hb + (size_t)(m0 + (f >> 4)) * NN_ + (f & 15) * 4);
        }
#pragma unroll
        for (int q = 0; q < 2; q++) {
            int r = br + 16 * q;
            rb[2 * q]     = *(const float4*)(orib + (size_t)(2 * r) * DD + bcq * 4);
            rb[2 * q + 1] = *(const float4*)(orib + (size_t)(2 * r + 1) * DD + bcq * 4);
        }
        {
            uint32_t* A0 = region; uint32_t* B0 = region + K1_ASZ;
#pragma unroll
            for (int p = 0; p < 8; p++) {
                int f = tid + p * 256;
                uint2 w; w.x = h2(ra[p].x, ra[p].y); w.y = h2(ra[p].z, ra[p].w);
                *(uint2*)&A0[(f >> 4) * K1_AW + (f & 15) * 2] = w;
            }
#pragma unroll
            for (int q = 0; q < 2; q++) {
                int r = br + 16 * q;
                uint4 w;
                w.x = h2(rb[2 * q].x, rb[2 * q + 1].x);
                w.y = h2(rb[2 * q].y, rb[2 * q + 1].y);
                w.z = h2(rb[2 * q].z, rb[2 * q + 1].z);
                w.w = h2(rb[2 * q].w, rb[2 * q + 1].w);
                *(uint4*)&B0[r * K1_BW + bcq * 4] = w;
            }
        }
        __syncthreads();

        int buf = 0;
        for (int k0 = 0; k0 < NN_; k0 += 64) {
            const int kn = k0 + 64;
            if (kn < NN_) {
#pragma unroll
                for (int p = 0; p < 8; p++) {
                    int f = tid + p * 256;
                    ra[p] = *(const float4*)(Hb + (size_t)(m0 + (f >> 4)) * NN_ + kn + (f & 15) * 4);
                }
#pragma unroll
                for (int q = 0; q < 2; q++) {
                    int r = br + 16 * q;
                    rb[2 * q]     = *(const float4*)(orib + (size_t)(kn + 2 * r) * DD + bcq * 4);
                    rb[2 * q + 1] = *(const float4*)(orib + (size_t)(kn + 2 * r + 1) * DD + bcq * 4);
                }
            }
            const uint32_t abase = smP1 + (uint32_t)(buf * (K1_BUF * 4));
            const uint32_t* B_ = region + buf * K1_BUF + K1_ASZ;
#pragma unroll
            for (int kk = 0; kk < 4; kk++) {
                uint32_t a0[4], a1[4], bf[4][2];
                ldsm4(a0[0], a0[1], a0[2], a0[3], abase + offA + kk * 32);
                ldsm4(a1[0], a1[1], a1[2], a1[3], abase + offA + 2304 + kk * 32);
#pragma unroll
                for (int ni = 0; ni < 4; ni++) {
                    bf[ni][0] = B_[(8 * kk + t) * K1_BW + wn1 + 8 * ni + g];
                    bf[ni][1] = B_[(8 * kk + t + 4) * K1_BW + wn1 + 8 * ni + g];
                }
#pragma unroll
                for (int ni = 0; ni < 4; ni++) {
                    mma16(acc[0][ni], a0[0], a0[1], a0[2], a0[3], bf[ni][0], bf[ni][1]);
                    mma16(acc[1][ni], a1[0], a1[1], a1[2], a1[3], bf[ni][0], bf[ni][1]);
                }
            }
            if (kn < NN_) {
                uint32_t* An = region + (buf ^ 1) * K1_BUF;
                uint32_t* Bn = An + K1_ASZ;
#pragma unroll
                for (int p = 0; p < 8; p++) {
                    int f = tid + p * 256;
                    uint2 w; w.x = h2(ra[p].x, ra[p].y); w.y = h2(ra[p].z, ra[p].w);
                    *(uint2*)&An[(f >> 4) * K1_AW + (f & 15) * 2] = w;
                }
#pragma unroll
                for (int q = 0; q < 2; q++) {
                    int r = br + 16 * q;
                    uint4 w;
                    w.x = h2(rb[2 * q].x, rb[2 * q + 1].x);
                    w.y = h2(rb[2 * q].y, rb[2 * q + 1].y);
                    w.z = h2(rb[2 * q].z, rb[2 * q + 1].z);
                    w.w = h2(rb[2 * q].w, rb[2 * q + 1].w);
                    *(uint4*)&Bn[r * K1_BW + bcq * 4] = w;
                }
            }
            __syncthreads();
            buf ^= 1;
        }

        // epilogue: pack acc -> Xs
#pragma unroll
        for (int mi = 0; mi < 2; mi++)
#pragma unroll
            for (int ni = 0; ni < 4; ni++) {
                int r1 = wm1 + 16 * mi + g, r2 = r1 + 8;
                int cw = (wn1 >> 1) + 4 * ni + t;
                Xs[r1 * 36 + cw] = h2(acc[mi][ni][0], acc[mi][ni][1]);
                Xs[r2 * 36 + cw] = h2(acc[mi][ni][2], acc[mi][ni][3]);
            }
    }
    // ================= phase 2 setup ========================================
    uint32_t* W1s = region;                    // 2 parity x [128][36w]
    uint32_t* W2s = region + 2 * W1_PW;        // 2 parity x [64][68w]
    float* wds = (float*)(W2s + 2 * W2_PW);    // [128][5]
    float* b1a = wds + 640;                    // [5][128]
    float* b2a = b1a + 640;                    // [5][64]

    const int wm2 = wid * 16;

    for (int f = tid; f < 640; f += 256) wds[f] = ed[row0 * TT + f];
    for (int f = tid; f < TT * HH; f += 256) b1a[f] = b1[f];
    for (int f = tid; f < TT * DD; f += 256) b2a[f] = b2[f];
    stage_w(0, 0, W1s, W2s, tid);
    __syncthreads();

    const uint32_t smX = sm_u32(Xs);
    const uint32_t offXA = ((wm2 + l15) * 36 + 4 * lq) * 4;
    uint32_t xa[4][4];
#pragma unroll
    for (int kc = 0; kc < 4; kc++)
        ldsm4(xa[kc][0], xa[kc][1], xa[kc][2], xa[kc][3], smX + offXA + kc * 32);

    float Y[8][4];
#pragma unroll
    for (int ni = 0; ni < 8; ni++)
#pragma unroll
        for (int jj = 0; jj < 4; jj++) Y[ni][jj] = 0.f;

    const int r1 = wm2 + g, r2 = wm2 + 8 + g;

    // lane base offsets for n-major B-frag LDSM (round-6 proven map)
    const uint32_t smW1b = sm_u32(W1s);
    const uint32_t smW2b = sm_u32(W2s);
    const uint32_t offW1 = ((8 * lq + lo) * 36 + 4 * lh) * 4;
    const uint32_t offW2 = ((8 * lq + lo) * 68 + 4 * lh) * 4;

    // ================= phase 2: 5-type MLP mixture (LDSM B-frags) ===========
    for (int et = 0; et < TT; et++) {
        const int pb = et & 1;
        if (et + 1 < TT) stage_w(et + 1, pb ^ 1, W1s, W2s, tid);

        const uint32_t w1base = smW1b + (uint32_t)(pb * (W1_PW * 4)) + offW1;
        const uint32_t w2base = smW2b + (uint32_t)(pb * (W2_PW * 4)) + offW2;

        const float wA = wds[r1 * TT + et];
        const float wB = wds[r2 * TT + et];

#pragma unroll
        for (int s = 0; s < 8; s++) {
            float h0a[4] = {0.f, 0.f, 0.f, 0.f};
            float h1a[4] = {0.f, 0.f, 0.f, 0.f};
#pragma unroll
            for (int kc = 0; kc < 4; kc++) {
                uint32_t bw[4];
                ldsm4(bw[0], bw[1], bw[2], bw[3],
                      w1base + (uint32_t)(s * (16 * 36 * 4)) + kc * 32);
                mma16(h0a, xa[kc][0], xa[kc][1], xa[kc][2], xa[kc][3], bw[0], bw[1]);
                mma16(h1a, xa[kc][0], xa[kc][1], xa[kc][2], xa[kc][3], bw[2], bw[3]);
            }
            float bx0 = b1a[et * HH + 16 * s + 2 * t];
            float by0 = b1a[et * HH + 16 * s + 2 * t + 1];
            float bx1 = b1a[et * HH + 16 * s + 8 + 2 * t];
            float by1 = b1a[et * HH + 16 * s + 8 + 2 * t + 1];
            uint32_t af0 = h2(wA * fmaxf(h0a[0] + bx0, 0.f), wA * fmaxf(h0a[1] + by0, 0.f));
            uint32_t af1 = h2(wB * fmaxf(h0a[2] + bx0, 0.f), wB * fmaxf(h0a[3] + by0, 0.f));
            uint32_t af2 = h2(wA * fmaxf(h1a[0] + bx1, 0.f), wA * fmaxf(h1a[1] + by1, 0.f));
            uint32_t af3 = h2(wB * fmaxf(h1a[2] + bx1, 0.f), wB * fmaxf(h1a[3] + by1, 0.f));
#pragma unroll
            for (int nb = 0; nb < 4; nb++) {
                uint32_t bw[4];
                ldsm4(bw[0], bw[1], bw[2], bw[3],
                      w2base + (uint32_t)(nb * (16 * 68 * 4)) + s * 32);
                mma16(Y[2 * nb],     af0, af1, af2, af3, bw[0], bw[1]);
                mma16(Y[2 * nb + 1], af0, af1, af2, af3, bw[2], bw[3]);
            }
        }
        __syncthreads();
    }

    // closed-form bias term: Y[r][c] += sum_t w[r][t] * b2[t][c]
    {
        float wv1[TT], wv2[TT];
#pragma unroll
        for (int t5 = 0; t5 < TT; t5++) {
            wv1[t5] = wds[r1 * TT + t5];
            wv2[t5] = wds[r2 * TT + t5];
        }
#pragma unroll
        for (int ni = 0; ni < 8; ni++) {
            int c = 8 * ni + 2 * t;
            float s0 = 0.f, s1 = 0.f, s2 = 0.f, s3 = 0.f;
#pragma unroll
            for (int t5 = 0; t5 < TT; t5++) {
                float bx = b2a[t5 * DD + c], by = b2a[t5 * DD + c + 1];
                s0 += wv1[t5] * bx; s1 += wv1[t5] * by;
                s2 += wv2[t5] * bx; s3 += wv2[t5] * by;
            }
            Y[ni][0] += s0; Y[ni][1] += s1;
            Y[ni][2] += s2; Y[ni][3] += s3;
        }
    }

    // epilogue -> g_efh
    {
        int gr1 = (int)row0 + r1, gr2 = (int)row0 + r2;
#pragma unroll
        for (int ni = 0; ni < 8; ni++) {
            g_efh[(size_t)gr1 * 32 + 4 * ni + t] = h2(Y[ni][0], Y[ni][1]);
            g_efh[(size_t)gr2 * 32 + 4 * ni + t] = h2(Y[ni][2], Y[ni][3]);
        }
    }

    // ori concat copy: CTA (b, tile) copies 64 node rows
    {
        const int n0 = (blockIdx.x & 7) * 64;
        const float* orib = ori + (size_t)b * NN_ * DD;
        float*       outb = out + (size_t)b * NN_ * (2 * DD);
#pragma unroll
        for (int p = 0; p < 4; p++) {
            int f = tid + p * 256;
            int r = f >> 4, cq = f & 15;
            float4 v = *(const float4*)(orib + (size_t)(n0 + r) * DD + cq * 4);
            *(float4*)(outb + (size_t)(n0 + r) * (2 * DD) + DD + cq * 4) = v;
        }
    }
}

// ---------------------------------------------------------------------------
// K3: node_agg = H^T @ ef (round-15 version, unchanged)
// ---------------------------------------------------------------------------
#define K3_HW 72
#define K3_BW 72
#define K3_HSZ (32 * K3_HW)
#define K3_BSZ (32 * K3_BW)
#define K3_BUF (K3_HSZ + K3_BSZ)
#define K3_SMEM_BYTES (2 * K3_BUF * 4)

__global__ __launch_bounds__(256) void k3_out(const float* __restrict__ H,
                                              float* __restrict__ out) {
    extern __shared__ uint32_t sw3[];

    const int b   = blockIdx.y;
    const int n0  = blockIdx.x * 64;
    const int tid = threadIdx.x;
    const int wid = tid >> 5, lane = tid & 31;
    const int g = lane >> 2, t = lane & 3;
    const int wm = (wid >> 1) * 16, wn = (wid & 1) * 32;

    const float* Hb = H + (size_t)b * EE * NN_;
    const uint32_t* efb = g_efh + (size_t)b * EE * 32;

    float acc[4][4];
#pragma unroll
    for (int ni = 0; ni < 4; ni++)
#pragma unroll
        for (int jj = 0; jj < 4; jj++) acc[ni][jj] = 0.f;

    const int hr = tid >> 4, hcq = tid & 15;

    float4 ha[4];
    uint2 eb[4];
#pragma unroll
    for (int q = 0; q < 2; q++) {
        int r = hr + 16 * q;
        ha[2 * q]     = *(const float4*)(Hb + (size_t)(2 * r) * NN_ + n0 + hcq * 4);
        ha[2 * q + 1] = *(const float4*)(Hb + (size_t)(2 * r + 1) * NN_ + n0 + hcq * 4);
        eb[2 * q]     = *(const uint2*)&efb[(size_t)(2 * r) * 32 + hcq * 2];
        eb[2 * q + 1] = *(const uint2*)&efb[(size_t)(2 * r + 1) * 32 + hcq * 2];
    }
    {
        uint32_t* Hp = sw3; uint32_t* Bp = sw3 + K3_HSZ;
#pragma unroll
        for (int q = 0; q < 2; q++) {
            int r = hr + 16 * q;
            uint4 wh;
            wh.x = h2(ha[2 * q].x, ha[2 * q + 1].x);
            wh.y = h2(ha[2 * q].y, ha[2 * q + 1].y);
            wh.z = h2(ha[2 * q].z, ha[2 * q + 1].z);
            wh.w = h2(ha[2 * q].w, ha[2 * q + 1].w);
            *(uint4*)&Hp[r * K3_HW + hcq * 4] = wh;
            uint4 wb;
            wb.x = __byte_perm(eb[2 * q].x, eb[2 * q + 1].x, 0x5410);
            wb.y = __byte_perm(eb[2 * q].x, eb[2 * q + 1].x, 0x7632);
            wb.z = __byte_perm(eb[2 * q].y, eb[2 * q + 1].y, 0x5410);
            wb.w = __byte_perm(eb[2 * q].y, eb[2 * q + 1].y, 0x7632);
            *(uint4*)&Bp[r * K3_BW + hcq * 4] = wb;
        }
    }
    __syncthreads();

    int buf = 0;
    for (int e0 = 0; e0 < EE; e0 += 64) {
        const int en = e0 + 64;
        if (en < EE) {
#pragma unroll
            for (int q = 0; q < 2; q++) {
                int r = hr + 16 * q;
                ha[2 * q]     = *(const float4*)(Hb + (size_t)(en + 2 * r) * NN_ + n0 + hcq * 4);
                ha[2 * q + 1] = *(const float4*)(Hb + (size_t)(en + 2 * r + 1) * NN_ + n0 + hcq * 4);
                eb[2 * q]     = *(const uint2*)&efb[(size_t)(en + 2 * r) * 32 + hcq * 2];
                eb[2 * q + 1] = *(const uint2*)&efb[(size_t)(en + 2 * r + 1) * 32 + hcq * 2];
            }
        }
        const uint32_t* Hp = sw3 + buf * K3_BUF;
        const uint32_t* Bp = Hp + K3_HSZ;
#pragma unroll
        for (int kk = 0; kk < 4; kk++) {
            uint32_t a[4], bf[4][2];
            a[0] = Hp[(8 * kk + t) * K3_HW + wm + g];
            a[1] = Hp[(8 * kk + t) * K3_HW + wm + 8 + g];
            a[2] = Hp[(8 * kk + t + 4) * K3_HW + wm + g];
            a[3] = Hp[(8 * kk + t + 4) * K3_HW + wm + 8 + g];
#pragma unroll
            for (int ni = 0; ni < 4; ni++) {
                bf[ni][0] = Bp[(8 * kk + t) * K3_BW + wn + 8 * ni + g];
                bf[ni][1] = Bp[(8 * kk + t + 4) * K3_BW + wn + 8 * ni + g];
            }
#pragma unroll
            for (int ni = 0; ni < 4; ni++)
                mma16(acc[ni], a[0], a[1], a[2], a[3], bf[ni][0], bf[ni][1]);
        }
        if (en < EE) {
            uint32_t* Hn = sw3 + (buf ^ 1) * K3_BUF;
            uint32_t* Bn = Hn + K3_HSZ;
#pragma unroll
            for (int q = 0; q < 2; q++) {
                int r = hr + 16 * q;
                uint4 wh;
                wh.x = h2(ha[2 * q].x, ha[2 * q + 1].x);
                wh.y = h2(ha[2 * q].y, ha[2 * q + 1].y);
                wh.z = h2(ha[2 * q].z, ha[2 * q + 1].z);
                wh.w = h2(ha[2 * q].w, ha[2 * q + 1].w);
                *(uint4*)&Hn[r * K3_HW + hcq * 4] = wh;
                uint4 wb;
                wb.x = __byte_perm(eb[2 * q].x, eb[2 * q + 1].x, 0x5410);
                wb.y = __byte_perm(eb[2 * q].x, eb[2 * q + 1].x, 0x7632);
                wb.z = __byte_perm(eb[2 * q].y, eb[2 * q + 1].y, 0x5410);
                wb.w = __byte_perm(eb[2 * q].y, eb[2 * q + 1].y, 0x7632);
                *(uint4*)&Bn[r * K3_BW + hcq * 4] = wb;
            }
        }
        __syncthreads();
        buf ^= 1;
    }

    float* outb = out + (size_t)b * NN_ * (2 * DD);
#pragma unroll
    for (int ni = 0; ni < 4; ni++) {
        int r1 = n0 + wm + g, r2 = r1 + 8;
        int c  = wn + 8 * ni + 2 * t;
        *(float2*)(outb + (size_t)r1 * (2 * DD) + c) =
            make_float2(acc[ni][0], acc[ni][1]);
        *(float2*)(outb + (size_t)r2 * (2 * DD) + c) =
            make_float2(acc[ni][2], acc[ni][3]);
    }
}

// ---------------------------------------------------------------------------
extern "C" void kernel_launch(void* const* d_in, const int* in_sizes, int n_in,
                              void* d_out, int out_size) {
    const float* ed  = (const float*)d_in[0];
    const float* H   = (const float*)d_in[1];
    const float* ori = (const float*)d_in[2];
    const float* W1  = (const float*)d_in[3];
    const float* b1  = (const float*)d_in[4];
    const float* W2  = (const float*)d_in[5];
    const float* b2  = (const float*)d_in[6];
    float* out = (float*)d_out;

    cudaFuncSetAttribute(kf_fused, cudaFuncAttributeMaxDynamicSharedMemorySize,
                         KF_SMEM_BYTES);

    k0_pack<<<80, 256>>>(W1, W2);

    kf_fused<<<(BB * EE) / 128, 256, KF_SMEM_BYTES>>>(H, ori, ed, b1, b2, out);

    dim3 g3(NN_ / 64, BB);
    k3_out<<<g3, 256, K3_SMEM_BYTES>>>(H, out);
}